// round 12
// baseline (speedup 1.0000x reference)
#include <cuda_runtime.h>
#include <math.h>
#include <stdint.h>

#define H 2048
#define E 64
#define TOPK 4
#define S 4096
#define SW 1024
#define NEGF (-3.4028234663852886e38f)   // float32 min
#define INV_SQRT_H 0.022097086912079608f // 1/sqrt(2048)

// scratch (device globals: allocation-free)
__device__ float g_wsT[H * E];    // K-major: g_wsT[h*E + e] = proj_w[e,h]*scale[h]*H^-0.5
__device__ int   g_gid[8 * S];    // vision group ids per (b, s)

// ---------------------------------------------------------------------------
// Kernel 1: fold scale & H^-0.5 into projection weights, TRANSPOSED to K-major
// ---------------------------------------------------------------------------
__global__ void ws_kernel(const float* __restrict__ proj_w,
                          const float* __restrict__ scale) {
    int i = blockIdx.x * blockDim.x + threadIdx.x;   // i = h*E + e
    if (i < E * H) {
        int h = i >> 6;
        int e = i & 63;
        g_wsT[i] = proj_w[e * H + h] * scale[h] * INV_SQRT_H;
    }
}

// ---------------------------------------------------------------------------
// Kernel 2: vision group ids (block-wide prefix scan, 1 block per batch row)
// ---------------------------------------------------------------------------
__global__ __launch_bounds__(1024) void gid_kernel(const int* __restrict__ mm) {
    int b = blockIdx.x;
    const int* row = mm + (size_t)b * S;
    int t = threadIdx.x;           // 1024 threads, 4 elems each
    int base = t * 4;

    int v[4];
    bool isv[4];
#pragma unroll
    for (int j = 0; j < 4; j++) {
        v[j] = row[base + j];
        isv[j] = (v[j] == 1) || (v[j] == 2);
    }
    bool prev = false;
    if (base > 0) {
        int p = row[base - 1];
        prev = (p == 1) || (p == 2);
    }
    int pre[4];
    int st[4];
    int cnt = 0;
#pragma unroll
    for (int j = 0; j < 4; j++) {
        st[j] = (isv[j] && !prev) ? 1 : 0;
        pre[j] = cnt;
        cnt += st[j];
        prev = isv[j];
    }

    __shared__ int sd[1024];
    sd[t] = cnt;
    __syncthreads();
    for (int off = 1; off < 1024; off <<= 1) {
        int val = sd[t];
        int add = (t >= off) ? sd[t - off] : 0;
        __syncthreads();
        sd[t] = val + add;
        __syncthreads();
    }
    int excl = sd[t] - cnt;
#pragma unroll
    for (int j = 0; j < 4; j++) {
        int incl = excl + pre[j] + st[j];
        g_gid[b * S + base + j] = isv[j] ? (incl - 1) : -1;
    }
}

// ---------------------------------------------------------------------------
// Fused kernel: blocks [0, ngate) run the gate (R7 path, FMA-bound);
//               blocks [ngate, ...) build the masks (HBM-store-bound).
// The two populations overlap on the GPU, hiding the mask's store time
// under the gate's compute time.
// ---------------------------------------------------------------------------
#define TM 64
#define KC 32
#define SXX 33                  // x tile row stride (floats)
#define SWW 68                  // w tile row stride (floats)
#define NCH (H / KC)            // 64 chunks
#define XSTG (TM * SXX)         // 2112 floats per x stage
#define WSTG (KC * SWW)         // 2176 floats per w stage
#define QT 4

// shared pool: gate needs 2*XSTG + 2*WSTG + TM = 8640 floats (34.56 KB)
//              mask needs 2*S ints (32 KB)
__global__ __launch_bounds__(256) void fused_kernel(const float* __restrict__ x,
                                                    const int* __restrict__ packed,
                                                    float* __restrict__ wout,
                                                    float* __restrict__ iout,
                                                    float* __restrict__ fullm,
                                                    float* __restrict__ slidm,
                                                    int ngate) {
    __shared__ __align__(16) float pool[2 * XSTG + 2 * WSTG + TM];

    const int t = threadIdx.x;

    if ((int)blockIdx.x >= ngate) {
        // =================== MASK PATH ===================
        int* sp = (int*)pool;
        int* sg = sp + S;

        const int mbid = blockIdx.x - ngate;
        const int nqb = S / QT;                 // 1024 blocks per batch
        const int b = mbid / nqb;
        const int qbase = (mbid % nqb) * QT;

        const int4* p4 = (const int4*)(packed + (size_t)b * S);
        const int4* g4 = (const int4*)(g_gid + (size_t)b * S);
        for (int i = t; i < S / 4; i += 256) {
            ((int4*)sp)[i] = p4[i];
            ((int4*)sg)[i] = g4[i];
        }
        __syncthreads();

#pragma unroll
        for (int qi = 0; qi < QT; qi++) {
            int q = qbase + qi;
            int pq = sp[q];
            int gq = sg[q];
            bool vq = (pq > 0);
            size_t rowoff = ((size_t)b * S + q) * (size_t)S;
            float4* fr = (float4*)(fullm + rowoff);
            float4* sr = (float4*)(slidm + rowoff);

            for (int i = t; i < S / 4; i += 256) {
                int kv = i * 4;
                float4 f, s;
                float* fp = (float*)&f;
                float* spv = (float*)&s;
#pragma unroll
                for (int j = 0; j < 4; j++) {
                    int k = kv + j;
                    int pk = sp[k];
                    int gk = sg[k];
                    bool same_doc = vq && (pq == pk);
                    bool causal = (k <= q);
                    bool fb = same_doc && causal;
                    bool win = (q - k) < SW;
                    bool svg = (gq >= 0) && (gq == gk);
                    bool sb = (fb && win) || (svg && same_doc);
                    fp[j]  = fb ? 0.0f : NEGF;
                    spv[j] = sb ? 0.0f : NEGF;
                }
                fr[i] = f;
                sr[i] = s;
            }
        }
        return;
    }

    // =================== GATE PATH (R7, 83.3us standalone) ===================
    float* smx = pool;                       // 2*XSTG
    float* smw = pool + 2 * XSTG;            // 2*WSTG
    float* ssh = pool + 2 * XSTG + 2 * WSTG; // TM

    const int n0 = blockIdx.x * TM;
    const int warp = t >> 5, lane = t & 31;
    const int tx = t & 15, ty = t >> 4;

    // x loader: two rows per thread, 4 consecutive k
    const int r0 = t >> 3, c0 = (t & 7) * 4;   // r0 in 0..31
    const int r1 = r0 + 32;
    const float* px0 = x + (size_t)(n0 + r0) * H + c0;
    const float* px1 = x + (size_t)(n0 + r1) * H + c0;
    const int sx0 = r0 * SXX + c0;
    const int sx1 = r1 * SXX + c0;

    // w loader: two K-rows per thread, 4 consecutive experts (g_wsT is [H][E])
    const int kw = t >> 4;                     // 0..15
    const int e4 = (t & 15) * 4;
    const float* pw0 = g_wsT + kw * E + e4;
    const float* pw1 = g_wsT + (kw + 16) * E + e4;
    const int sw0 = kw * SWW + e4;
    const int sw1 = (kw + 16) * SWW + e4;

    if (t < TM) ssh[t] = 0.0f;

    float ssa = 0.0f, ssb = 0.0f;

    // prologue: chunk 0 -> stage 0
    {
        float4 lx0 = *(const float4*)px0;
        float4 lx1 = *(const float4*)px1;
        float4 lw0 = *(const float4*)pw0;
        float4 lw1 = *(const float4*)pw1;
        smx[sx0 + 0] = lx0.x; smx[sx0 + 1] = lx0.y; smx[sx0 + 2] = lx0.z; smx[sx0 + 3] = lx0.w;
        smx[sx1 + 0] = lx1.x; smx[sx1 + 1] = lx1.y; smx[sx1 + 2] = lx1.z; smx[sx1 + 3] = lx1.w;
        *(float4*)(smw + sw0) = lw0;
        *(float4*)(smw + sw1) = lw1;
        ssa += lx0.x*lx0.x + lx0.y*lx0.y + lx0.z*lx0.z + lx0.w*lx0.w;
        ssb += lx1.x*lx1.x + lx1.y*lx1.y + lx1.z*lx1.z + lx1.w*lx1.w;
    }
    __syncthreads();

    float acc[4][4];
#pragma unroll
    for (int i = 0; i < 4; i++)
#pragma unroll
        for (int j = 0; j < 4; j++) acc[i][j] = 0.f;

    for (int c = 0; c < NCH; c++) {
        const int s = c & 1;
        float4 nx0, nx1, nw0, nw1;
        const bool more = (c + 1 < NCH);
        if (more) {
            const int kox = (c + 1) * KC;               // x advances along H
            nx0 = *(const float4*)(px0 + kox);
            nx1 = *(const float4*)(px1 + kox);
            const int kow = (c + 1) * KC * E;           // w advances KC rows of E
            nw0 = *(const float4*)(pw0 + kow);
            nw1 = *(const float4*)(pw1 + kow);
        }

        const float* xb = smx + s * XSTG + (ty * 4) * SXX;
        const float* wb = smw + s * WSTG + tx * 4;
#pragma unroll 8
        for (int k = 0; k < KC; k++) {
            float4 b = *(const float4*)(wb + k * SWW);
            float a0 = xb[0 * SXX + k];
            float a1 = xb[1 * SXX + k];
            float a2 = xb[2 * SXX + k];
            float a3 = xb[3 * SXX + k];
            acc[0][0] += a0 * b.x; acc[0][1] += a0 * b.y; acc[0][2] += a0 * b.z; acc[0][3] += a0 * b.w;
            acc[1][0] += a1 * b.x; acc[1][1] += a1 * b.y; acc[1][2] += a1 * b.z; acc[1][3] += a1 * b.w;
            acc[2][0] += a2 * b.x; acc[2][1] += a2 * b.y; acc[2][2] += a2 * b.z; acc[2][3] += a2 * b.w;
            acc[3][0] += a3 * b.x; acc[3][1] += a3 * b.y; acc[3][2] += a3 * b.z; acc[3][3] += a3 * b.w;
        }

        if (more) {
            __syncthreads();
            const int dx = (s ^ 1) * XSTG;
            const int dw = (s ^ 1) * WSTG;
            smx[dx + sx0 + 0] = nx0.x; smx[dx + sx0 + 1] = nx0.y;
            smx[dx + sx0 + 2] = nx0.z; smx[dx + sx0 + 3] = nx0.w;
            smx[dx + sx1 + 0] = nx1.x; smx[dx + sx1 + 1] = nx1.y;
            smx[dx + sx1 + 2] = nx1.z; smx[dx + sx1 + 3] = nx1.w;
            *(float4*)(smw + dw + sw0) = nw0;
            *(float4*)(smw + dw + sw1) = nw1;
            ssa += nx0.x*nx0.x + nx0.y*nx0.y + nx0.z*nx0.z + nx0.w*nx0.w;
            ssb += nx1.x*nx1.x + nx1.y*nx1.y + nx1.z*nx1.z + nx1.w*nx1.w;
            __syncthreads();
        }
    }

    atomicAdd(&ssh[r0], ssa);
    atomicAdd(&ssh[r1], ssb);
    __syncthreads();

    // logits -> reuse smx as [64][65]
    float* lsm = smx;
#pragma unroll
    for (int i = 0; i < 4; i++) {
        const int m = ty * 4 + i;
        const float iv = rsqrtf(ssh[m] * (1.0f / H) + 1e-6f);
#pragma unroll
        for (int j = 0; j < 4; j++)
            lsm[m * 65 + tx * 4 + j] = acc[i][j] * iv;
    }
    __syncthreads();

    // ---- top-4 per token (warp handles 8 tokens; 2 experts per lane) ----
#pragma unroll
    for (int i = 0; i < TM / 8; i++) {
        int tok = warp * 8 + i;
        float l0 = lsm[tok * 65 + lane];
        float l1 = lsm[tok * 65 + lane + 32];
        float m = fmaxf(l0, l1);
#pragma unroll
        for (int off = 16; off > 0; off >>= 1)
            m = fmaxf(m, __shfl_xor_sync(0xffffffffu, m, off));
        float e0 = __expf(l0 - m);
        float e1 = __expf(l1 - m);

        float wv[TOPK];
        int widx[TOPK];
        float wsum = 0.f;
#pragma unroll
        for (int r = 0; r < TOPK; r++) {
            float v; int idx;
            if (e0 >= e1) { v = e0; idx = lane; }
            else          { v = e1; idx = lane + 32; }
#pragma unroll
            for (int off = 16; off > 0; off >>= 1) {
                float ov = __shfl_xor_sync(0xffffffffu, v, off);
                int oi = __shfl_xor_sync(0xffffffffu, idx, off);
                if (ov > v || (ov == v && oi < idx)) { v = ov; idx = oi; }
            }
            wv[r] = v; widx[r] = idx; wsum += v;
            if (idx == lane)      e0 = -1.f;
            if (idx == lane + 32) e1 = -1.f;
        }
        if (lane == 0) {
            float inv = 1.f / fmaxf(wsum, 1e-20f);
            int o = (n0 + tok) * TOPK;
#pragma unroll
            for (int r = 0; r < TOPK; r++) {
                wout[o + r] = wv[r] * inv;
                iout[o + r] = (float)widx[r];
            }
        }
    }
}

// ---------------------------------------------------------------------------
extern "C" void kernel_launch(void* const* d_in, const int* in_sizes, int n_in,
                              void* d_out, int out_size) {
    const float* x      = (const float*)d_in[0];
    const int*   packed = (const int*)d_in[1];
    const int*   mm     = (const int*)d_in[2];
    const float* scale  = (const float*)d_in[3];
    const float* proj_w = (const float*)d_in[4];

    int Ntok = in_sizes[1];           // B*S
    int B = Ntok / S;

    float* out = (float*)d_out;
    size_t mask_elems = (size_t)B * S * S;
    float* fullm = out;
    float* slidm = out + mask_elems;
    float* wout  = out + 2 * mask_elems;
    float* iout  = wout + (size_t)Ntok * TOPK;

    int ngate = Ntok / TM;                      // 128 gate blocks
    int nmask = B * (S / QT);                   // 2048 mask blocks

    ws_kernel<<<(E * H + 255) / 256, 256>>>(proj_w, scale);
    gid_kernel<<<B, 1024>>>(mm);
    fused_kernel<<<ngate + nmask, 256>>>(x, packed, wout, iout, fullm, slidm, ngate);
}

// round 13
// speedup vs baseline: 1.0388x; 1.0388x over previous
#include <cuda_runtime.h>
#include <math.h>
#include <stdint.h>

#define H 2048
#define E 64
#define TOPK 4
#define S 4096
#define SW 1024
#define NEGF (-3.4028234663852886e38f)   // float32 min
#define INV_SQRT_H 0.022097086912079608f // 1/sqrt(2048)

// scratch (device globals: allocation-free)
__device__ float g_wsT[H * E];    // K-major: g_wsT[h*E + e] = proj_w[e,h]*scale[h]*H^-0.5
__device__ int   g_gid[8 * S];    // vision group ids per (b, s)

// ---------------------------------------------------------------------------
// Kernel 1: fold scale & H^-0.5 into projection weights, TRANSPOSED to K-major
// ---------------------------------------------------------------------------
__global__ void ws_kernel(const float* __restrict__ proj_w,
                          const float* __restrict__ scale) {
    int i = blockIdx.x * blockDim.x + threadIdx.x;   // i = h*E + e
    if (i < E * H) {
        int h = i >> 6;
        int e = i & 63;
        g_wsT[i] = proj_w[e * H + h] * scale[h] * INV_SQRT_H;
    }
}

// ---------------------------------------------------------------------------
// Kernel 2: vision group ids (block-wide prefix scan, 1 block per batch row)
// ---------------------------------------------------------------------------
__global__ __launch_bounds__(1024) void gid_kernel(const int* __restrict__ mm) {
    int b = blockIdx.x;
    const int* row = mm + (size_t)b * S;
    int t = threadIdx.x;           // 1024 threads, 4 elems each
    int base = t * 4;

    int v[4];
    bool isv[4];
#pragma unroll
    for (int j = 0; j < 4; j++) {
        v[j] = row[base + j];
        isv[j] = (v[j] == 1) || (v[j] == 2);
    }
    bool prev = false;
    if (base > 0) {
        int p = row[base - 1];
        prev = (p == 1) || (p == 2);
    }
    int pre[4];
    int st[4];
    int cnt = 0;
#pragma unroll
    for (int j = 0; j < 4; j++) {
        st[j] = (isv[j] && !prev) ? 1 : 0;
        pre[j] = cnt;
        cnt += st[j];
        prev = isv[j];
    }

    __shared__ int sd[1024];
    sd[t] = cnt;
    __syncthreads();
    for (int off = 1; off < 1024; off <<= 1) {
        int val = sd[t];
        int add = (t >= off) ? sd[t - off] : 0;
        __syncthreads();
        sd[t] = val + add;
        __syncthreads();
    }
    int excl = sd[t] - cnt;
#pragma unroll
    for (int j = 0; j < 4; j++) {
        int incl = excl + pre[j] + st[j];
        g_gid[b * S + base + j] = isv[j] ? (incl - 1) : -1;
    }
}

// ---------------------------------------------------------------------------
// Kernel 3: build full + sliding additive masks
// ---------------------------------------------------------------------------
#define QT 4
__global__ __launch_bounds__(256) void mask_kernel(const int* __restrict__ packed,
                                                   float* __restrict__ fullm,
                                                   float* __restrict__ slidm) {
    __shared__ int sp[S];
    __shared__ int sg[S];

    const int nqb = S / QT;                    // 1024 blocks per batch
    int b = blockIdx.x / nqb;
    int qbase = (blockIdx.x % nqb) * QT;

    const int4* p4 = (const int4*)(packed + (size_t)b * S);
    const int4* g4 = (const int4*)(g_gid + (size_t)b * S);
    for (int i = threadIdx.x; i < S / 4; i += 256) {
        ((int4*)sp)[i] = p4[i];
        ((int4*)sg)[i] = g4[i];
    }
    __syncthreads();

#pragma unroll
    for (int qi = 0; qi < QT; qi++) {
        int q = qbase + qi;
        int pq = sp[q];
        int gq = sg[q];
        bool vq = (pq > 0);
        size_t rowoff = ((size_t)b * S + q) * (size_t)S;
        float4* fr = (float4*)(fullm + rowoff);
        float4* sr = (float4*)(slidm + rowoff);

        for (int i = threadIdx.x; i < S / 4; i += 256) {
            int kv = i * 4;
            float4 f, s;
            float* fp = (float*)&f;
            float* spv = (float*)&s;
#pragma unroll
            for (int j = 0; j < 4; j++) {
                int k = kv + j;
                int pk = sp[k];
                int gk = sg[k];
                bool same_doc = vq && (pq == pk);
                bool causal = (k <= q);
                bool fb = same_doc && causal;
                bool win = (q - k) < SW;
                bool svg = (gq >= 0) && (gq == gk);
                bool sb = (fb && win) || (svg && same_doc);
                fp[j]  = fb ? 0.0f : NEGF;
                spv[j] = sb ? 0.0f : NEGF;
            }
            fr[i] = f;
            sr[i] = s;
        }
    }
}

// ---------------------------------------------------------------------------
// Kernel 4: gate. TM=32 tokens x 64 experts per block, 128 threads,
//   grid = 256 -> ~2 independent CTAs per SM (better issue hiding, no idle SMs).
//   Same validated micro-kernel as R7: 4 tok x 4 exp per thread,
//   KC=32 double-buffered, conflict-free smem layouts.
// ---------------------------------------------------------------------------
#define TM 32
#define KC 32
#define SXX 33                  // x tile row stride (floats)
#define SWW 68                  // w tile row stride (floats)
#define NCH (H / KC)            // 64 chunks
#define XSTG (TM * SXX)         // 1056 floats per x stage
#define WSTG (KC * SWW)         // 2176 floats per w stage

__global__ __launch_bounds__(128) void gate_kernel(const float* __restrict__ x,
                                                   float* __restrict__ wout,
                                                   float* __restrict__ iout) {
    __shared__ float smx[2 * XSTG];     // x tiles (reused for logits at the end)
    __shared__ float smw[2 * WSTG];     // w tiles (K-major)
    __shared__ float ssh[TM];           // per-token sum of squares

    const int t = threadIdx.x;
    const int n0 = blockIdx.x * TM;
    const int warp = t >> 5, lane = t & 31;
    const int tx = t & 15, ty = t >> 4;        // 16 x 8 thread grid

    // x loader: row = t&31 (all 32 rows distinct per warp -> conflict-free STS),
    //           cols (t>>5)*8 .. +7 (two float4)
    const int r0 = t & 31;
    const int c0 = (t >> 5) * 8;
    const float* px0 = x + (size_t)(n0 + r0) * H + c0;     // float4 at c0
    const float* px1 = px0 + 4;                            // float4 at c0+4
    const int sx0 = r0 * SXX + c0;
    const int sx1 = sx0 + 4;

    // w loader: 4 float4 per chunk: rows kw+8q, col e4 (g_wsT is [H][E])
    const int kw = t >> 4;                     // 0..7
    const int e4 = (t & 15) * 4;
    const float* pw = g_wsT + kw * E + e4;
    const int sw = kw * SWW + e4;

    if (t < TM) ssh[t] = 0.0f;

    float ssa = 0.0f;

    // prologue: chunk 0 -> stage 0
    {
        float4 lx0 = *(const float4*)px0;
        float4 lx1 = *(const float4*)px1;
        smx[sx0 + 0] = lx0.x; smx[sx0 + 1] = lx0.y; smx[sx0 + 2] = lx0.z; smx[sx0 + 3] = lx0.w;
        smx[sx1 + 0] = lx1.x; smx[sx1 + 1] = lx1.y; smx[sx1 + 2] = lx1.z; smx[sx1 + 3] = lx1.w;
        ssa += lx0.x*lx0.x + lx0.y*lx0.y + lx0.z*lx0.z + lx0.w*lx0.w;
        ssa += lx1.x*lx1.x + lx1.y*lx1.y + lx1.z*lx1.z + lx1.w*lx1.w;
#pragma unroll
        for (int q = 0; q < 4; q++) {
            float4 w = *(const float4*)(pw + q * 8 * E);
            *(float4*)(smw + sw + q * 8 * SWW) = w;
        }
    }
    __syncthreads();

    float acc[4][4];
#pragma unroll
    for (int i = 0; i < 4; i++)
#pragma unroll
        for (int j = 0; j < 4; j++) acc[i][j] = 0.f;

    for (int c = 0; c < NCH; c++) {
        const int s = c & 1;
        float4 nx0, nx1, nw[4];
        const bool more = (c + 1 < NCH);
        if (more) {
            const int kox = (c + 1) * KC;               // x advances along H
            nx0 = *(const float4*)(px0 + kox);
            nx1 = *(const float4*)(px1 + kox);
            const int kow = (c + 1) * KC * E;           // w advances KC rows of E
#pragma unroll
            for (int q = 0; q < 4; q++)
                nw[q] = *(const float4*)(pw + kow + q * 8 * E);
        }

        const float* xb = smx + s * XSTG + (ty * 4) * SXX;
        const float* wb = smw + s * WSTG + tx * 4;
#pragma unroll 8
        for (int k = 0; k < KC; k++) {
            float4 b = *(const float4*)(wb + k * SWW);
            float a0 = xb[0 * SXX + k];
            float a1 = xb[1 * SXX + k];
            float a2 = xb[2 * SXX + k];
            float a3 = xb[3 * SXX + k];
            acc[0][0] += a0 * b.x; acc[0][1] += a0 * b.y; acc[0][2] += a0 * b.z; acc[0][3] += a0 * b.w;
            acc[1][0] += a1 * b.x; acc[1][1] += a1 * b.y; acc[1][2] += a1 * b.z; acc[1][3] += a1 * b.w;
            acc[2][0] += a2 * b.x; acc[2][1] += a2 * b.y; acc[2][2] += a2 * b.z; acc[2][3] += a2 * b.w;
            acc[3][0] += a3 * b.x; acc[3][1] += a3 * b.y; acc[3][2] += a3 * b.z; acc[3][3] += a3 * b.w;
        }

        if (more) {
            __syncthreads();
            const int dx = (s ^ 1) * XSTG;
            const int dw = (s ^ 1) * WSTG;
            smx[dx + sx0 + 0] = nx0.x; smx[dx + sx0 + 1] = nx0.y;
            smx[dx + sx0 + 2] = nx0.z; smx[dx + sx0 + 3] = nx0.w;
            smx[dx + sx1 + 0] = nx1.x; smx[dx + sx1 + 1] = nx1.y;
            smx[dx + sx1 + 2] = nx1.z; smx[dx + sx1 + 3] = nx1.w;
            ssa += nx0.x*nx0.x + nx0.y*nx0.y + nx0.z*nx0.z + nx0.w*nx0.w;
            ssa += nx1.x*nx1.x + nx1.y*nx1.y + nx1.z*nx1.z + nx1.w*nx1.w;
#pragma unroll
            for (int q = 0; q < 4; q++)
                *(float4*)(smw + dw + sw + q * 8 * SWW) = nw[q];
            __syncthreads();
        }
    }

    atomicAdd(&ssh[r0], ssa);
    __syncthreads();

    // logits -> reuse smx as [32][65]
    float* lsm = smx;
#pragma unroll
    for (int i = 0; i < 4; i++) {
        const int m = ty * 4 + i;
        const float iv = rsqrtf(ssh[m] * (1.0f / H) + 1e-6f);
#pragma unroll
        for (int j = 0; j < 4; j++)
            lsm[m * 65 + tx * 4 + j] = acc[i][j] * iv;
    }
    __syncthreads();

    // ---- top-4 per token (4 warps x 8 tokens; 2 experts per lane) ----
#pragma unroll
    for (int i = 0; i < TM / 4; i++) {
        int tok = warp * 8 + i;
        float l0 = lsm[tok * 65 + lane];
        float l1 = lsm[tok * 65 + lane + 32];
        float m = fmaxf(l0, l1);
#pragma unroll
        for (int off = 16; off > 0; off >>= 1)
            m = fmaxf(m, __shfl_xor_sync(0xffffffffu, m, off));
        float e0 = __expf(l0 - m);
        float e1 = __expf(l1 - m);

        float wv[TOPK];
        int widx[TOPK];
        float wsum = 0.f;
#pragma unroll
        for (int r = 0; r < TOPK; r++) {
            float v; int idx;
            if (e0 >= e1) { v = e0; idx = lane; }
            else          { v = e1; idx = lane + 32; }
#pragma unroll
            for (int off = 16; off > 0; off >>= 1) {
                float ov = __shfl_xor_sync(0xffffffffu, v, off);
                int oi = __shfl_xor_sync(0xffffffffu, idx, off);
                if (ov > v || (ov == v && oi < idx)) { v = ov; idx = oi; }
            }
            wv[r] = v; widx[r] = idx; wsum += v;
            if (idx == lane)      e0 = -1.f;
            if (idx == lane + 32) e1 = -1.f;
        }
        if (lane == 0) {
            float inv = 1.f / fmaxf(wsum, 1e-20f);
            int o = (n0 + tok) * TOPK;
#pragma unroll
            for (int r = 0; r < TOPK; r++) {
                wout[o + r] = wv[r] * inv;
                iout[o + r] = (float)widx[r];
            }
        }
    }
}

// ---------------------------------------------------------------------------
extern "C" void kernel_launch(void* const* d_in, const int* in_sizes, int n_in,
                              void* d_out, int out_size) {
    const float* x      = (const float*)d_in[0];
    const int*   packed = (const int*)d_in[1];
    const int*   mm     = (const int*)d_in[2];
    const float* scale  = (const float*)d_in[3];
    const float* proj_w = (const float*)d_in[4];

    int Ntok = in_sizes[1];           // B*S
    int B = Ntok / S;

    float* out = (float*)d_out;
    size_t mask_elems = (size_t)B * S * S;
    float* fullm = out;
    float* slidm = out + mask_elems;
    float* wout  = out + 2 * mask_elems;
    float* iout  = wout + (size_t)Ntok * TOPK;

    ws_kernel<<<(E * H + 255) / 256, 256>>>(proj_w, scale);
    gid_kernel<<<B, 1024>>>(mm);
    mask_kernel<<<B * (S / QT), 256>>>(packed, fullm, slidm);
    gate_kernel<<<Ntok / TM, 128>>>(x, wout, iout);
}

// round 14
// speedup vs baseline: 1.2374x; 1.1912x over previous
#include <cuda_runtime.h>
#include <math.h>
#include <stdint.h>

#define H 2048
#define E 64
#define TOPK 4
#define S 4096
#define SW 1024
#define NEGF (-3.4028234663852886e38f)   // float32 min
#define INV_SQRT_H 0.022097086912079608f // 1/sqrt(2048)

// scratch (device globals: allocation-free)
__device__ float g_wsT[H * E];    // K-major: g_wsT[h*E + e] = proj_w[e,h]*scale[h]*H^-0.5
__device__ int   g_gid[8 * S];    // vision group ids per (b, s)

// ---------------------------------------------------------------------------
// Prep kernel (merged): blocks [0, nws) fold+transpose weights;
//                       blocks [nws, nws+B) run the gid prefix scan.
// Both paths are register-light, so heterogeneous fusion is safe here.
// ---------------------------------------------------------------------------
__global__ __launch_bounds__(1024) void prep_kernel(const float* __restrict__ proj_w,
                                                    const float* __restrict__ scale,
                                                    const int* __restrict__ mm,
                                                    int nws) {
    __shared__ int sd[1024];

    if ((int)blockIdx.x < nws) {
        // ---- ws path: 1024 threads, 4 elems each ----
        int base = blockIdx.x * 4096 + threadIdx.x;
#pragma unroll
        for (int j = 0; j < 4; j++) {
            int i = base + j * 1024;                 // i = h*E + e
            if (i < E * H) {
                int h = i >> 6;
                int e = i & 63;
                g_wsT[i] = proj_w[e * H + h] * scale[h] * INV_SQRT_H;
            }
        }
        return;
    }

    // ---- gid path: block-wide prefix scan, 1 block per batch row ----
    int b = blockIdx.x - nws;
    const int* row = mm + (size_t)b * S;
    int t = threadIdx.x;           // 1024 threads, 4 elems each
    int base = t * 4;

    int v[4];
    bool isv[4];
#pragma unroll
    for (int j = 0; j < 4; j++) {
        v[j] = row[base + j];
        isv[j] = (v[j] == 1) || (v[j] == 2);
    }
    bool prev = false;
    if (base > 0) {
        int p = row[base - 1];
        prev = (p == 1) || (p == 2);
    }
    int pre[4];
    int st[4];
    int cnt = 0;
#pragma unroll
    for (int j = 0; j < 4; j++) {
        st[j] = (isv[j] && !prev) ? 1 : 0;
        pre[j] = cnt;
        cnt += st[j];
        prev = isv[j];
    }

    sd[t] = cnt;
    __syncthreads();
    for (int off = 1; off < 1024; off <<= 1) {
        int val = sd[t];
        int add = (t >= off) ? sd[t - off] : 0;
        __syncthreads();
        sd[t] = val + add;
        __syncthreads();
    }
    int excl = sd[t] - cnt;
#pragma unroll
    for (int j = 0; j < 4; j++) {
        int incl = excl + pre[j] + st[j];
        g_gid[b * S + base + j] = isv[j] ? (incl - 1) : -1;
    }
}

// ---------------------------------------------------------------------------
// Mask kernel: build full + sliding additive masks (HBM-write-bound)
// ---------------------------------------------------------------------------
#define QT 4
__global__ __launch_bounds__(256) void mask_kernel(const int* __restrict__ packed,
                                                   float* __restrict__ fullm,
                                                   float* __restrict__ slidm) {
    __shared__ int sp[S];
    __shared__ int sg[S];

    const int nqb = S / QT;                    // 1024 blocks per batch
    int b = blockIdx.x / nqb;
    int qbase = (blockIdx.x % nqb) * QT;

    const int4* p4 = (const int4*)(packed + (size_t)b * S);
    const int4* g4 = (const int4*)(g_gid + (size_t)b * S);
    for (int i = threadIdx.x; i < S / 4; i += 256) {
        ((int4*)sp)[i] = p4[i];
        ((int4*)sg)[i] = g4[i];
    }
    __syncthreads();

#pragma unroll
    for (int qi = 0; qi < QT; qi++) {
        int q = qbase + qi;
        int pq = sp[q];
        int gq = sg[q];
        bool vq = (pq > 0);
        size_t rowoff = ((size_t)b * S + q) * (size_t)S;
        float4* fr = (float4*)(fullm + rowoff);
        float4* sr = (float4*)(slidm + rowoff);

        for (int i = threadIdx.x; i < S / 4; i += 256) {
            int kv = i * 4;
            float4 f, s;
            float* fp = (float*)&f;
            float* spv = (float*)&s;
#pragma unroll
            for (int j = 0; j < 4; j++) {
                int k = kv + j;
                int pk = sp[k];
                int gk = sg[k];
                bool same_doc = vq && (pq == pk);
                bool causal = (k <= q);
                bool fb = same_doc && causal;
                bool win = (q - k) < SW;
                bool svg = (gq >= 0) && (gq == gk);
                bool sb = (fb && win) || (svg && same_doc);
                fp[j]  = fb ? 0.0f : NEGF;
                spv[j] = sb ? 0.0f : NEGF;
            }
            fr[i] = f;
            sr[i] = s;
        }
    }
}

// ---------------------------------------------------------------------------
// Gate kernel (R7 datapath + single-sync double buffering).
//   64 tokens x 64 experts per block, KC=32, 256 threads, grid=128.
//   Loop: store regs->stage(c&1); ONE sync; prefetch c+1; compute stage(c&1).
//   Stores always hit the stage not being computed -> second barrier removed.
// ---------------------------------------------------------------------------
#define TM 64
#define KC 32
#define SXX 33                  // x tile row stride (floats)
#define SWW 68                  // w tile row stride (floats)
#define NCH (H / KC)            // 64 chunks
#define XSTG (TM * SXX)         // 2112 floats per x stage
#define WSTG (KC * SWW)         // 2176 floats per w stage

__global__ __launch_bounds__(256, 1) void gate_kernel(const float* __restrict__ x,
                                                      float* __restrict__ wout,
                                                      float* __restrict__ iout) {
    __shared__ float smx[2 * XSTG];     // x tiles (reused for logits at the end)
    __shared__ float smw[2 * WSTG];     // w tiles (K-major)
    __shared__ float ssh[TM];           // per-token sum of squares

    const int t = threadIdx.x;
    const int n0 = blockIdx.x * TM;
    const int warp = t >> 5, lane = t & 31;
    const int tx = t & 15, ty = t >> 4;

    // x loader: two rows per thread, 4 consecutive k
    const int r0 = t >> 3, c0 = (t & 7) * 4;   // r0 in 0..31
    const int r1 = r0 + 32;
    const float* px0 = x + (size_t)(n0 + r0) * H + c0;
    const float* px1 = x + (size_t)(n0 + r1) * H + c0;
    const int sx0 = r0 * SXX + c0;
    const int sx1 = r1 * SXX + c0;

    // w loader: two K-rows per thread, 4 consecutive experts (g_wsT is [H][E])
    const int kw = t >> 4;                     // 0..15
    const int e4 = (t & 15) * 4;
    const float* pw0 = g_wsT + kw * E + e4;
    const float* pw1 = g_wsT + (kw + 16) * E + e4;
    const int sw0 = kw * SWW + e4;
    const int sw1 = (kw + 16) * SWW + e4;

    if (t < TM) ssh[t] = 0.0f;

    float ssa = 0.0f, ssb = 0.0f;

    // regs hold chunk-c data at the top of iteration c
    float4 cx0 = *(const float4*)px0;
    float4 cx1 = *(const float4*)px1;
    float4 cw0 = *(const float4*)pw0;
    float4 cw1 = *(const float4*)pw1;

    float acc[4][4];
#pragma unroll
    for (int i = 0; i < 4; i++)
#pragma unroll
        for (int j = 0; j < 4; j++) acc[i][j] = 0.f;

    for (int c = 0; c < NCH; c++) {
        const int s = c & 1;
        const int dx = s * XSTG;
        const int dw = s * WSTG;

        // ---- store current chunk to stage s (other stage may still be computed on) ----
        smx[dx + sx0 + 0] = cx0.x; smx[dx + sx0 + 1] = cx0.y;
        smx[dx + sx0 + 2] = cx0.z; smx[dx + sx0 + 3] = cx0.w;
        smx[dx + sx1 + 0] = cx1.x; smx[dx + sx1 + 1] = cx1.y;
        smx[dx + sx1 + 2] = cx1.z; smx[dx + sx1 + 3] = cx1.w;
        *(float4*)(smw + dw + sw0) = cw0;
        *(float4*)(smw + dw + sw1) = cw1;
        ssa += cx0.x*cx0.x + cx0.y*cx0.y + cx0.z*cx0.z + cx0.w*cx0.w;
        ssb += cx1.x*cx1.x + cx1.y*cx1.y + cx1.z*cx1.z + cx1.w*cx1.w;

        __syncthreads();   // stage s fully written; safe to compute it

        // ---- prefetch chunk c+1 into regs (overlaps compute below) ----
        if (c + 1 < NCH) {
            const int kox = (c + 1) * KC;
            cx0 = *(const float4*)(px0 + kox);
            cx1 = *(const float4*)(px1 + kox);
            const int kow = (c + 1) * KC * E;
            cw0 = *(const float4*)(pw0 + kow);
            cw1 = *(const float4*)(pw1 + kow);
        }

        // ---- compute stage s ----
        const float* xb = smx + dx + (ty * 4) * SXX;
        const float* wb = smw + dw + tx * 4;
#pragma unroll 8
        for (int k = 0; k < KC; k++) {
            float4 b = *(const float4*)(wb + k * SWW);
            float a0 = xb[0 * SXX + k];
            float a1 = xb[1 * SXX + k];
            float a2 = xb[2 * SXX + k];
            float a3 = xb[3 * SXX + k];
            acc[0][0] += a0 * b.x; acc[0][1] += a0 * b.y; acc[0][2] += a0 * b.z; acc[0][3] += a0 * b.w;
            acc[1][0] += a1 * b.x; acc[1][1] += a1 * b.y; acc[1][2] += a1 * b.z; acc[1][3] += a1 * b.w;
            acc[2][0] += a2 * b.x; acc[2][1] += a2 * b.y; acc[2][2] += a2 * b.z; acc[2][3] += a2 * b.w;
            acc[3][0] += a3 * b.x; acc[3][1] += a3 * b.y; acc[3][2] += a3 * b.z; acc[3][3] += a3 * b.w;
        }
        // next iteration stores to stage s^1 — no second barrier needed
    }

    atomicAdd(&ssh[r0], ssa);
    atomicAdd(&ssh[r1], ssb);
    __syncthreads();

    // logits -> reuse smx as [64][65]
    float* lsm = smx;
#pragma unroll
    for (int i = 0; i < 4; i++) {
        const int m = ty * 4 + i;
        const float iv = rsqrtf(ssh[m] * (1.0f / H) + 1e-6f);
#pragma unroll
        for (int j = 0; j < 4; j++)
            lsm[m * 65 + tx * 4 + j] = acc[i][j] * iv;
    }
    __syncthreads();

    // ---- top-4 per token (warp handles 8 tokens; 2 experts per lane) ----
#pragma unroll
    for (int i = 0; i < TM / 8; i++) {
        int tok = warp * 8 + i;
        float l0 = lsm[tok * 65 + lane];
        float l1 = lsm[tok * 65 + lane + 32];
        float m = fmaxf(l0, l1);
#pragma unroll
        for (int off = 16; off > 0; off >>= 1)
            m = fmaxf(m, __shfl_xor_sync(0xffffffffu, m, off));
        float e0 = __expf(l0 - m);
        float e1 = __expf(l1 - m);

        float wv[TOPK];
        int widx[TOPK];
        float wsum = 0.f;
#pragma unroll
        for (int r = 0; r < TOPK; r++) {
            float v; int idx;
            if (e0 >= e1) { v = e0; idx = lane; }
            else          { v = e1; idx = lane + 32; }
#pragma unroll
            for (int off = 16; off > 0; off >>= 1) {
                float ov = __shfl_xor_sync(0xffffffffu, v, off);
                int oi = __shfl_xor_sync(0xffffffffu, idx, off);
                if (ov > v || (ov == v && oi < idx)) { v = ov; idx = oi; }
            }
            wv[r] = v; widx[r] = idx; wsum += v;
            if (idx == lane)      e0 = -1.f;
            if (idx == lane + 32) e1 = -1.f;
        }
        if (lane == 0) {
            float inv = 1.f / fmaxf(wsum, 1e-20f);
            int o = (n0 + tok) * TOPK;
#pragma unroll
            for (int r = 0; r < TOPK; r++) {
                wout[o + r] = wv[r] * inv;
                iout[o + r] = (float)widx[r];
            }
        }
    }
}

// ---------------------------------------------------------------------------
extern "C" void kernel_launch(void* const* d_in, const int* in_sizes, int n_in,
                              void* d_out, int out_size) {
    const float* x      = (const float*)d_in[0];
    const int*   packed = (const int*)d_in[1];
    const int*   mm     = (const int*)d_in[2];
    const float* scale  = (const float*)d_in[3];
    const float* proj_w = (const float*)d_in[4];

    int Ntok = in_sizes[1];           // B*S
    int B = Ntok / S;

    float* out = (float*)d_out;
    size_t mask_elems = (size_t)B * S * S;
    float* fullm = out;
    float* slidm = out + mask_elems;
    float* wout  = out + 2 * mask_elems;
    float* iout  = wout + (size_t)Ntok * TOPK;

    int nws = (E * H + 4095) / 4096;            // 32 ws blocks
    prep_kernel<<<nws + B, 1024>>>(proj_w, scale, mm, nws);
    mask_kernel<<<B * (S / QT), 256>>>(packed, fullm, slidm);
    gate_kernel<<<Ntok / TM, 256>>>(x, wout, iout);
}